// round 15
// baseline (speedup 1.0000x reference)
#include <cuda_runtime.h>
#include <cuda_fp16.h>
#include <cstdint>

// Problem constants (fixed by the dataset)
#define N_NODES 10000
#define N_EDGES 320000
#define D_FEAT  128
#define OUT_DIM 128
#define SCALES  3
#define KDIM    384
#define NTILES  (N_EDGES / 128)   // 2500

// ---------------------------------------------------------------------------
// Device globals
// ---------------------------------------------------------------------------
__device__ __align__(16) uint32_t g_NAh[N_NODES * 192];
__device__ __align__(16) uint32_t g_NBh[N_NODES * 192];
__device__ __align__(16) uint32_t g_nfh[N_NODES * 64];
__device__ __align__(16) uint32_t g_W1kp[6 * 64 * 136];
// W2 n-major fp16 image: row r = s*128+k (384 rows), 68 words/row.
__device__ __align__(16) uint32_t g_W2nm[384 * 68];
__device__ __align__(16) float g_b2m[128];
__device__ __align__(16) float c_W1g[SCALES * 128];
__device__ __align__(16) float c_b1g[SCALES * 128];
__device__ int g_idx64;

// ---------------------------------------------------------------------------
// Baseline-PTX helpers (compile for plain sm_103)
// ---------------------------------------------------------------------------
__device__ __forceinline__ uint32_t smem_to_u32(const void* p) {
    uint32_t a;
    asm("{ .reg .u64 t; cvta.to.shared.u64 t, %1; cvt.u32.u64 %0, t; }" : "=r"(a) : "l"(p));
    return a;
}

#define LDSM_X4(r, addr) \
    asm volatile("ldmatrix.sync.aligned.m8n8.x4.shared.b16 {%0,%1,%2,%3}, [%4];" \
        : "=r"((r)[0]), "=r"((r)[1]), "=r"((r)[2]), "=r"((r)[3]) : "r"(addr))

#define LDSM_X4T(r, addr) \
    asm volatile("ldmatrix.sync.aligned.m8n8.x4.trans.shared.b16 {%0,%1,%2,%3}, [%4];" \
        : "=r"((r)[0]), "=r"((r)[1]), "=r"((r)[2]), "=r"((r)[3]) : "r"(addr))

__device__ __forceinline__ void mma_f16(float c[4], const uint32_t a[4],
                                        uint32_t b0, uint32_t b1) {
    asm volatile(
        "mma.sync.aligned.m16n8k16.row.col.f32.f16.f16.f32 "
        "{%0,%1,%2,%3}, {%4,%5,%6,%7}, {%8,%9}, {%0,%1,%2,%3};"
        : "+f"(c[0]), "+f"(c[1]), "+f"(c[2]), "+f"(c[3])
        : "r"(a[0]), "r"(a[1]), "r"(a[2]), "r"(a[3]), "r"(b0), "r"(b1));
}

__device__ __forceinline__ uint32_t pack_h2(float lo, float hi) {
    __half2 h = __floats2half2_rn(lo, hi);
    return *(uint32_t*)&h;
}
__device__ __forceinline__ float2 h2f2(uint32_t w) {
    return __half22float2(*(__half2*)&w);
}

// ---------------------------------------------------------------------------
// Kernel 0: single prep kernel. Grid-strided task ranges:
//   [0, 160000)          : nf -> fp16 k-pair quads
//   [160000, 212224)     : W1 halves -> k-pair images (52224)
//   [212224, 238336)     : W2 -> n-major image (26112)
//   [238336, 238720)     : c_W1g / c_b1g (384)
//   [238720, 238848)     : g_b2m (128)
// Block 0 additionally: dtype detect (threads 0-127).
// ---------------------------------------------------------------------------
#define PREP_BLOCKS 933

__global__ void prep_all_kernel(const float* __restrict__ nf,
                                const float* __restrict__ W1,
                                const float* __restrict__ W2,
                                const float* __restrict__ b1,
                                const float* __restrict__ b2,
                                const int* __restrict__ ei_raw) {
    int gidx = blockIdx.x * 256 + threadIdx.x;

    if (gidx < 160000) {
        float4 v0 = ((const float4*)nf)[2 * gidx];
        float4 v1 = ((const float4*)nf)[2 * gidx + 1];
        uint4 o;
        o.x = pack_h2(v0.x, v0.y);
        o.y = pack_h2(v0.z, v0.w);
        o.z = pack_h2(v1.x, v1.y);
        o.w = pack_h2(v1.z, v1.w);
        ((uint4*)g_nfh)[gidx] = o;
    } else if (gidx < 212224) {
        int id = gidx - 160000;
        int p  = id / 8704;
        int r  = id - p * 8704;
        int kp = r / 136;
        int n  = r - kp * 136;
        uint32_t v = 0;
        if (n < 128) {
            int s = p >> 1, half = p & 1;
            const float* base = W1 + s * (257 * 128) + (half * 128 + 2 * kp) * 128 + n;
            v = pack_h2(base[0], base[128]);
        }
        g_W1kp[id] = v;
    } else if (gidx < 238336) {
        int id = gidx - 212224;          // 0..26111
        int r = id / 68, n2 = id - r * 68;   // r = s*128+k
        uint32_t v = 0;
        if (n2 < 64) {
            float2 w = *(const float2*)(W2 + r * 128 + n2 * 2);
            v = pack_h2(w.x, w.y);
        }
        g_W2nm[id] = v;
    } else if (gidx < 238720) {
        int t = gidx - 238336;     // 0..383
        int s = t >> 7, n = t & 127;
        c_W1g[t] = W1[s * (257 * 128) + 256 * 128 + n];
        c_b1g[t] = b1[t];
    } else if (gidx < 238848) {
        int n = gidx - 238720;     // 0..127
        g_b2m[n] = (b2[n] + b2[128 + n] + b2[256 + n]) * (1.0f / 3.0f);
    }

    if (blockIdx.x == 0) {
        int t = threadIdx.x;
        int nz = (t < 128 && ei_raw[2 * t + 1] != 0) ? 1 : 0;
        int tot = __syncthreads_count(nz);
        if (t == 0) g_idx64 = (tot == 0) ? 1 : 0;
    }
}

// ---------------------------------------------------------------------------
// Kernel 1: node precompute via fp16 MMA (fp32 accumulate).
// grid = (79, 6): blockIdx.x -> 128-node tile, blockIdx.y = part p.
// ---------------------------------------------------------------------------
#define NP_ROWB  272
#define NP_SMW   34816
#define NP_TOT   (34816 + 64 * 136 * 4)   // 69632

__global__ __launch_bounds__(256, 2)
void node_pre_kernel() {
    extern __shared__ char smem[];
    const uint32_t smem_u = smem_to_u32(smem);
    uint32_t* smW = (uint32_t*)(smem + NP_SMW);

    const int tid  = threadIdx.x;
    const int wid  = tid >> 5;
    const int lane = tid & 31;
    const int gid  = lane >> 2;
    const int qid  = lane & 3;
    const int p    = blockIdx.y;
    const int n0   = blockIdx.x * 128;

    for (int i = tid; i < 2048; i += 256) {
        int row = i >> 4, c4 = i & 15;
        uint4 v = make_uint4(0, 0, 0, 0);
        if (n0 + row < N_NODES)
            v = *(const uint4*)(g_nfh + (size_t)(n0 + row) * 64 + c4 * 4);
        *(uint4*)(smem + row * NP_ROWB + c4 * 16) = v;
    }
    {
        const uint32_t* src = g_W1kp + p * 8704;
        for (int i = tid; i < 8704; i += 256) smW[i] = src[i];
    }
    __syncthreads();

    const int m0  = (wid >> 1) * 32;
    const int nc0 = (wid & 1) * 64;
    const int arow = m0 + (lane & 7) + 8 * ((lane >> 3) & 1);
    const uint32_t acb = (uint32_t)(((lane >> 4) & 1) * 16);

    float acc[2][8][4];
    #pragma unroll
    for (int mi = 0; mi < 2; mi++)
        #pragma unroll
        for (int g = 0; g < 8; g++)
            #pragma unroll
            for (int q = 0; q < 4; q++) acc[mi][g][q] = 0.f;

    #pragma unroll
    for (int ks = 0; ks < 8; ks++) {
        uint32_t a0f[4], a1f[4];
        LDSM_X4(a0f, smem_u + (uint32_t)(arow * NP_ROWB) + (uint32_t)(ks * 32) + acb);
        LDSM_X4(a1f, smem_u + (uint32_t)((arow + 16) * NP_ROWB) + (uint32_t)(ks * 32) + acb);
        const uint32_t* bp = smW + (ks * 8 + qid) * 136 + nc0 + gid;
        #pragma unroll
        for (int g = 0; g < 8; g++) {
            uint32_t b0 = bp[g * 8];
            uint32_t b1 = bp[g * 8 + 4 * 136];
            mma_f16(acc[0][g], a0f, b0, b1);
            mma_f16(acc[1][g], a1f, b0, b1);
        }
    }

    uint32_t* outg = (p & 1) ? g_NBh : g_NAh;
    const int s = p >> 1;
    #pragma unroll
    for (int mi = 0; mi < 2; mi++) {
        const int row = n0 + m0 + mi * 16 + gid;
        #pragma unroll
        for (int g = 0; g < 8; g++) {
            int cw = s * 64 + (nc0 >> 1) + g * 4 + qid;
            if (row < N_NODES)
                outg[(size_t)row * 192 + cw] = pack_h2(acc[mi][g][0], acc[mi][g][1]);
            if (row + 8 < N_NODES)
                outg[(size_t)(row + 8) * 192 + cw] = pack_h2(acc[mi][g][2], acc[mi][g][3]);
        }
    }
}

// ---------------------------------------------------------------------------
// Kernel 2: warp-specialized fp16 mma edge kernel (R12 structure, unroll 4).
// Single change vs R12: producer sources (si, di, gap) from registers
// prefetched one tile ahead (lane-parallel idx+gap loads at s==0), and the
// row loop reads them via __shfl_sync instead of 3 broadcast LDGs.
// Per-row chain: shuffle -> gather LDG (1 L2 hop instead of 3).
// ---------------------------------------------------------------------------
#define H_ROWB   272
#define W2_ROWB  272
#define SMEM_W2  0                 // 384*272 = 104448
#define SMEM_H0  104448            // 128*272 = 34816
#define SMEM_H1  139264
#define SMEM_TOT 174080

__global__ __launch_bounds__(512, 1)
void edge_kernel(const float* __restrict__ temporal,
                 const void* __restrict__ ei,
                 float* __restrict__ out) {
    extern __shared__ char smem[];
    const uint32_t smem_u = smem_to_u32(smem);

    const int tid  = threadIdx.x;
    const int wid  = tid >> 5;
    const int lane = tid & 31;
    const int gid  = lane >> 2;
    const int qid  = lane & 3;
    const int role = wid >> 3;                     // 0 = consumer, 1 = producer

    // Stage W2 n-major image into smem once.
    {
        const uint4* src = (const uint4*)g_W2nm;
        uint4* dst = (uint4*)(smem + SMEM_W2);
        for (int i = tid; i < 384 * 68 / 4; i += 512) dst[i] = src[i];
    }
    __syncthreads();

    // Consumer constants
    const int m0   = (wid >> 1) * 32;
    const int nc0  = (wid & 1) * 64;
    const int arow = m0 + (lane & 7) + 8 * ((lane >> 3) & 1);
    const uint32_t acb = (uint32_t)(((lane >> 4) & 1) * 16);
    const int g2 = lane >> 3, rr = lane & 7;
    const uint32_t b_lane = smem_u + SMEM_W2
        + (uint32_t)(((g2 & 1) * 8 + rr) * W2_ROWB + (nc0 + (g2 >> 1) * 8) * 2);

    // Producer constants
    const int pw = wid - 8;

    const int idx64 = g_idx64;
    const float inv3 = 1.0f / 3.0f;

    int nt = 0;
    for (int tt = blockIdx.x; tt < NTILES; tt += 148) nt++;

    // Producer prefetch registers: lane r (r<16; lanes 16-31 duplicate) holds
    // (si, di, gap) for edge row pw*16 + r of the prefetched tile.
    int   si_pf = 0, di_pf = 0;
    float gap_pf = 0.f;
    int   si_cur = 0, di_cur = 0;
    float gap_cur = 0.f;
    if (role == 1) {
        const int e0n  = blockIdx.x * 128;
        const int rown = pw * 16 + (lane & 15);
        if (idx64) {
            si_pf = (int)((const long long*)ei)[e0n + rown];
            di_pf = (int)((const long long*)ei)[N_EDGES + e0n + rown];
        } else {
            si_pf = ((const int*)ei)[e0n + rown];
            di_pf = ((const int*)ei)[N_EDGES + e0n + rown];
        }
        gap_pf = temporal[si_pf] - temporal[di_pf];
    }

    float acc[2][8][4];
    #pragma unroll
    for (int mi = 0; mi < 2; mi++)
        #pragma unroll
        for (int g = 0; g < 8; g++)
            #pragma unroll
            for (int q = 0; q < 4; q++) acc[mi][g][q] = 0.f;

    const int P = 3 * nt + 1;
    for (int j = 0; j < P; j++) {
        if (role == 1 && j < 3 * nt) {
            // ---- producer: build H for phase j ----
            const int tile = j / 3;
            const int s    = j - 3 * tile;
            char* hb = smem + ((j & 1) ? SMEM_H1 : SMEM_H0);

            if (s == 0) {
                // Rotate prefetched tile into current; prefetch next tile.
                si_cur = si_pf; di_cur = di_pf; gap_cur = gap_pf;
                int ntt = blockIdx.x + (tile + 1) * 148;
                if (ntt >= NTILES) ntt = blockIdx.x + tile * 148;
                const int e0n  = ntt * 128;
                const int rown = pw * 16 + (lane & 15);
                if (idx64) {
                    si_pf = (int)((const long long*)ei)[e0n + rown];
                    di_pf = (int)((const long long*)ei)[N_EDGES + e0n + rown];
                } else {
                    si_pf = ((const int*)ei)[e0n + rown];
                    di_pf = ((const int*)ei)[N_EDGES + e0n + rown];
                }
                gap_pf = temporal[si_pf] - temporal[di_pf];
            }

            const float4 gv = *(const float4*)(c_W1g + s * 128 + lane * 4);
            const float4 bv = *(const float4*)(c_b1g + s * 128 + lane * 4);

            #pragma unroll 4
            for (int r = 0; r < 16; r++) {
                const int row = pw * 16 + r;
                const int   si  = __shfl_sync(0xffffffffu, si_cur, r);
                const int   di  = __shfl_sync(0xffffffffu, di_cur, r);
                const float gap = __shfl_sync(0xffffffffu, gap_cur, r);
                uint2 na = *((const uint2*)(g_NAh + (size_t)si * 192 + s * 64) + lane);
                uint2 nb = *((const uint2*)(g_NBh + (size_t)di * 192 + s * 64) + lane);
                float2 a0 = h2f2(na.x), a1 = h2f2(na.y);
                float2 c0 = h2f2(nb.x), c1 = h2f2(nb.y);
                float h0 = fmaxf(a0.x + c0.x + fmaf(gap, gv.x, bv.x), 0.f);
                float h1 = fmaxf(a0.y + c0.y + fmaf(gap, gv.y, bv.y), 0.f);
                float h2 = fmaxf(a1.x + c1.x + fmaf(gap, gv.z, bv.z), 0.f);
                float h3 = fmaxf(a1.y + c1.y + fmaf(gap, gv.w, bv.w), 0.f);
                uint2 ho;
                ho.x = pack_h2(h0, h1);
                ho.y = pack_h2(h2, h3);
                *(uint2*)(hb + row * H_ROWB + lane * 8) = ho;
            }
        }
        if (role == 0 && j >= 1) {
            // ---- consumer: MMA for phase j-1 (R12 verbatim) ----
            const int jj   = j - 1;
            const int tile = jj / 3;
            const int s    = jj - 3 * tile;
            const uint32_t Hb = smem_u + ((jj & 1) ? SMEM_H1 : SMEM_H0);
            const uint32_t Bb = b_lane + (uint32_t)(s * 128 * W2_ROWB);

            #pragma unroll
            for (int ks = 0; ks < 8; ks++) {
                uint32_t a0f[4], a1f[4];
                LDSM_X4(a0f, Hb + (uint32_t)(arow * H_ROWB) + (uint32_t)(ks * 32) + acb);
                LDSM_X4(a1f, Hb + (uint32_t)((arow + 16) * H_ROWB) + (uint32_t)(ks * 32) + acb);
                const uint32_t bks = Bb + (uint32_t)(ks * 16 * W2_ROWB);
                #pragma unroll
                for (int np = 0; np < 4; np++) {
                    uint32_t b[4];
                    LDSM_X4T(b, bks + (uint32_t)(np * 32));
                    mma_f16(acc[0][np * 2],     a0f, b[0], b[1]);
                    mma_f16(acc[0][np * 2 + 1], a0f, b[2], b[3]);
                    mma_f16(acc[1][np * 2],     a1f, b[0], b[1]);
                    mma_f16(acc[1][np * 2 + 1], a1f, b[2], b[3]);
                }
            }

            if (s == 2) {
                const size_t e0o = (size_t)(blockIdx.x + tile * 148) * 128;
                #pragma unroll
                for (int mi = 0; mi < 2; mi++) {
                    const size_t r0 = e0o + m0 + mi * 16 + gid;
                    #pragma unroll
                    for (int g = 0; g < 8; g++) {
                        int col = nc0 + g * 8 + qid * 2;
                        float2 bm = *(const float2*)(g_b2m + col);
                        *(float2*)(out + r0 * 128 + col) =
                            make_float2(acc[mi][g][0] * inv3 + bm.x,
                                        acc[mi][g][1] * inv3 + bm.y);
                        *(float2*)(out + (r0 + 8) * 128 + col) =
                            make_float2(acc[mi][g][2] * inv3 + bm.x,
                                        acc[mi][g][3] * inv3 + bm.y);
                        #pragma unroll
                        for (int q = 0; q < 4; q++) acc[mi][g][q] = 0.f;
                    }
                }
            }
        }
        __syncthreads();
    }
}

// ---------------------------------------------------------------------------
// Launch
// ---------------------------------------------------------------------------
extern "C" void kernel_launch(void* const* d_in, const int* in_sizes, int n_in,
                              void* d_out, int out_size) {
    const float* nf = 0;
    const float* temporal = 0;
    const float* W1 = 0;
    const float* b1 = 0;
    const float* W2 = 0;
    const float* b2 = 0;
    const void*  ei = 0;

    for (int i = 0; i < n_in; i++) {
        switch (in_sizes[i]) {
            case N_NODES * D_FEAT:   nf = (const float*)d_in[i]; break;
            case N_NODES:            temporal = (const float*)d_in[i]; break;
            case SCALES * 257 * 128: W1 = (const float*)d_in[i]; break;
            case SCALES * 128 * 128: W2 = (const float*)d_in[i]; break;
            case 2 * N_EDGES:        ei = d_in[i]; break;
            case SCALES * 128:
                if (!b1) b1 = (const float*)d_in[i];
                else     b2 = (const float*)d_in[i];
                break;
            default: break;
        }
    }
    float* out = (float*)d_out;

    cudaFuncSetAttribute(node_pre_kernel, cudaFuncAttributeMaxDynamicSharedMemorySize, NP_TOT);
    cudaFuncSetAttribute(edge_kernel,     cudaFuncAttributeMaxDynamicSharedMemorySize, SMEM_TOT);

    prep_all_kernel<<<PREP_BLOCKS, 256>>>(nf, W1, W2, b1, b2, (const int*)ei);

    dim3 g1(79, 6);
    node_pre_kernel<<<g1, 256, NP_TOT>>>();

    edge_kernel<<<148, 512, SMEM_TOT>>>(temporal, ei, out);
}

// round 16
// speedup vs baseline: 1.1049x; 1.1049x over previous
#include <cuda_runtime.h>
#include <cuda_fp16.h>
#include <cstdint>

// Problem constants (fixed by the dataset)
#define N_NODES 10000
#define N_EDGES 320000
#define D_FEAT  128
#define OUT_DIM 128
#define SCALES  3
#define KDIM    384
#define NTILES  (N_EDGES / 128)   // 2500

// ---------------------------------------------------------------------------
// Device globals
// ---------------------------------------------------------------------------
__device__ __align__(16) uint32_t g_NAh[N_NODES * 192];
__device__ __align__(16) uint32_t g_NBh[N_NODES * 192];
__device__ __align__(16) uint32_t g_nfh[N_NODES * 64];
__device__ __align__(16) uint32_t g_W1kp[6 * 64 * 136];
// W2 n-major fp16 image: row r = s*128+k (384 rows), 68 words/row.
__device__ __align__(16) uint32_t g_W2nm[384 * 68];
__device__ __align__(16) float g_b2m[128];
__device__ __align__(16) float c_W1g[SCALES * 128];
__device__ __align__(16) float c_b1g[SCALES * 128];
__device__ int g_idx64;

// ---------------------------------------------------------------------------
// Baseline-PTX helpers (compile for plain sm_103)
// ---------------------------------------------------------------------------
__device__ __forceinline__ uint32_t smem_to_u32(const void* p) {
    uint32_t a;
    asm("{ .reg .u64 t; cvta.to.shared.u64 t, %1; cvt.u32.u64 %0, t; }" : "=r"(a) : "l"(p));
    return a;
}

#define LDSM_X4(r, addr) \
    asm volatile("ldmatrix.sync.aligned.m8n8.x4.shared.b16 {%0,%1,%2,%3}, [%4];" \
        : "=r"((r)[0]), "=r"((r)[1]), "=r"((r)[2]), "=r"((r)[3]) : "r"(addr))

#define LDSM_X4T(r, addr) \
    asm volatile("ldmatrix.sync.aligned.m8n8.x4.trans.shared.b16 {%0,%1,%2,%3}, [%4];" \
        : "=r"((r)[0]), "=r"((r)[1]), "=r"((r)[2]), "=r"((r)[3]) : "r"(addr))

// Named barriers: producers/consumers, 512 = 256 arrivals + 256 syncs.
#define BAR_SYNC(id)   asm volatile("bar.sync %0, 512;"   :: "r"(id) : "memory")
#define BAR_ARRIVE(id) asm volatile("bar.arrive %0, 512;" :: "r"(id) : "memory")

__device__ __forceinline__ void mma_f16(float c[4], const uint32_t a[4],
                                        uint32_t b0, uint32_t b1) {
    asm volatile(
        "mma.sync.aligned.m16n8k16.row.col.f32.f16.f16.f32 "
        "{%0,%1,%2,%3}, {%4,%5,%6,%7}, {%8,%9}, {%0,%1,%2,%3};"
        : "+f"(c[0]), "+f"(c[1]), "+f"(c[2]), "+f"(c[3])
        : "r"(a[0]), "r"(a[1]), "r"(a[2]), "r"(a[3]), "r"(b0), "r"(b1));
}

__device__ __forceinline__ uint32_t pack_h2(float lo, float hi) {
    __half2 h = __floats2half2_rn(lo, hi);
    return *(uint32_t*)&h;
}
__device__ __forceinline__ float2 h2f2(uint32_t w) {
    return __half22float2(*(__half2*)&w);
}

// ---------------------------------------------------------------------------
// Kernel 0: single prep kernel (unchanged from R12).
// ---------------------------------------------------------------------------
#define PREP_BLOCKS 933

__global__ void prep_all_kernel(const float* __restrict__ nf,
                                const float* __restrict__ W1,
                                const float* __restrict__ W2,
                                const float* __restrict__ b1,
                                const float* __restrict__ b2,
                                const int* __restrict__ ei_raw) {
    int gidx = blockIdx.x * 256 + threadIdx.x;

    if (gidx < 160000) {
        float4 v0 = ((const float4*)nf)[2 * gidx];
        float4 v1 = ((const float4*)nf)[2 * gidx + 1];
        uint4 o;
        o.x = pack_h2(v0.x, v0.y);
        o.y = pack_h2(v0.z, v0.w);
        o.z = pack_h2(v1.x, v1.y);
        o.w = pack_h2(v1.z, v1.w);
        ((uint4*)g_nfh)[gidx] = o;
    } else if (gidx < 212224) {
        int id = gidx - 160000;
        int p  = id / 8704;
        int r  = id - p * 8704;
        int kp = r / 136;
        int n  = r - kp * 136;
        uint32_t v = 0;
        if (n < 128) {
            int s = p >> 1, half = p & 1;
            const float* base = W1 + s * (257 * 128) + (half * 128 + 2 * kp) * 128 + n;
            v = pack_h2(base[0], base[128]);
        }
        g_W1kp[id] = v;
    } else if (gidx < 238336) {
        int id = gidx - 212224;          // 0..26111
        int r = id / 68, n2 = id - r * 68;   // r = s*128+k
        uint32_t v = 0;
        if (n2 < 64) {
            float2 w = *(const float2*)(W2 + r * 128 + n2 * 2);
            v = pack_h2(w.x, w.y);
        }
        g_W2nm[id] = v;
    } else if (gidx < 238720) {
        int t = gidx - 238336;     // 0..383
        int s = t >> 7, n = t & 127;
        c_W1g[t] = W1[s * (257 * 128) + 256 * 128 + n];
        c_b1g[t] = b1[t];
    } else if (gidx < 238848) {
        int n = gidx - 238720;     // 0..127
        g_b2m[n] = (b2[n] + b2[128 + n] + b2[256 + n]) * (1.0f / 3.0f);
    }

    if (blockIdx.x == 0) {
        int t = threadIdx.x;
        int nz = (t < 128 && ei_raw[2 * t + 1] != 0) ? 1 : 0;
        int tot = __syncthreads_count(nz);
        if (t == 0) g_idx64 = (tot == 0) ? 1 : 0;
    }
}

// ---------------------------------------------------------------------------
// Kernel 1: node precompute via fp16 MMA (unchanged from R12).
// ---------------------------------------------------------------------------
#define NP_ROWB  272
#define NP_SMW   34816
#define NP_TOT   (34816 + 64 * 136 * 4)   // 69632

__global__ __launch_bounds__(256, 2)
void node_pre_kernel() {
    extern __shared__ char smem[];
    const uint32_t smem_u = smem_to_u32(smem);
    uint32_t* smW = (uint32_t*)(smem + NP_SMW);

    const int tid  = threadIdx.x;
    const int wid  = tid >> 5;
    const int lane = tid & 31;
    const int gid  = lane >> 2;
    const int qid  = lane & 3;
    const int p    = blockIdx.y;
    const int n0   = blockIdx.x * 128;

    for (int i = tid; i < 2048; i += 256) {
        int row = i >> 4, c4 = i & 15;
        uint4 v = make_uint4(0, 0, 0, 0);
        if (n0 + row < N_NODES)
            v = *(const uint4*)(g_nfh + (size_t)(n0 + row) * 64 + c4 * 4);
        *(uint4*)(smem + row * NP_ROWB + c4 * 16) = v;
    }
    {
        const uint32_t* src = g_W1kp + p * 8704;
        for (int i = tid; i < 8704; i += 256) smW[i] = src[i];
    }
    __syncthreads();

    const int m0  = (wid >> 1) * 32;
    const int nc0 = (wid & 1) * 64;
    const int arow = m0 + (lane & 7) + 8 * ((lane >> 3) & 1);
    const uint32_t acb = (uint32_t)(((lane >> 4) & 1) * 16);

    float acc[2][8][4];
    #pragma unroll
    for (int mi = 0; mi < 2; mi++)
        #pragma unroll
        for (int g = 0; g < 8; g++)
            #pragma unroll
            for (int q = 0; q < 4; q++) acc[mi][g][q] = 0.f;

    #pragma unroll
    for (int ks = 0; ks < 8; ks++) {
        uint32_t a0f[4], a1f[4];
        LDSM_X4(a0f, smem_u + (uint32_t)(arow * NP_ROWB) + (uint32_t)(ks * 32) + acb);
        LDSM_X4(a1f, smem_u + (uint32_t)((arow + 16) * NP_ROWB) + (uint32_t)(ks * 32) + acb);
        const uint32_t* bp = smW + (ks * 8 + qid) * 136 + nc0 + gid;
        #pragma unroll
        for (int g = 0; g < 8; g++) {
            uint32_t b0 = bp[g * 8];
            uint32_t b1 = bp[g * 8 + 4 * 136];
            mma_f16(acc[0][g], a0f, b0, b1);
            mma_f16(acc[1][g], a1f, b0, b1);
        }
    }

    uint32_t* outg = (p & 1) ? g_NBh : g_NAh;
    const int s = p >> 1;
    #pragma unroll
    for (int mi = 0; mi < 2; mi++) {
        const int row = n0 + m0 + mi * 16 + gid;
        #pragma unroll
        for (int g = 0; g < 8; g++) {
            int cw = s * 64 + (nc0 >> 1) + g * 4 + qid;
            if (row < N_NODES)
                outg[(size_t)row * 192 + cw] = pack_h2(acc[mi][g][0], acc[mi][g][1]);
            if (row + 8 < N_NODES)
                outg[(size_t)(row + 8) * 192 + cw] = pack_h2(acc[mi][g][2], acc[mi][g][3]);
        }
    }
}

// ---------------------------------------------------------------------------
// Kernel 2: warp-specialized fp16 mma edge kernel.
// Bodies are R12-verbatim. Sync scaffolding changed from lockstep
// __syncthreads to named producer/consumer barriers:
//   A(1+b): buf b filled   (producers bar.arrive, consumers bar.sync)
//   B(3+b): buf b consumed (consumers bar.arrive post-MMA, producers
//           bar.sync before refilling; skipped for j<2)
// Consumer arrives B BEFORE its epilogue, overlapping producer refill
// with epilogue global stores.
// ---------------------------------------------------------------------------
#define H_ROWB   272
#define W2_ROWB  272
#define SMEM_W2  0                 // 384*272 = 104448
#define SMEM_H0  104448            // 128*272 = 34816
#define SMEM_H1  139264
#define SMEM_TOT 174080

__global__ __launch_bounds__(512, 1)
void edge_kernel(const float* __restrict__ temporal,
                 const void* __restrict__ ei,
                 float* __restrict__ out) {
    extern __shared__ char smem[];
    const uint32_t smem_u = smem_to_u32(smem);

    const int tid  = threadIdx.x;
    const int wid  = tid >> 5;
    const int lane = tid & 31;
    const int gid  = lane >> 2;
    const int qid  = lane & 3;
    const int role = wid >> 3;                     // 0 = consumer, 1 = producer

    // Stage W2 n-major image into smem once.
    {
        const uint4* src = (const uint4*)g_W2nm;
        uint4* dst = (uint4*)(smem + SMEM_W2);
        for (int i = tid; i < 384 * 68 / 4; i += 512) dst[i] = src[i];
    }
    __syncthreads();

    const int idx64 = g_idx64;
    const float inv3 = 1.0f / 3.0f;

    int nt = 0;
    for (int tt = blockIdx.x; tt < NTILES; tt += 148) nt++;
    const int NP = 3 * nt;

    if (role == 1) {
        // =====================  PRODUCER  =====================
        const int pw = wid - 8;

        for (int j = 0; j < NP; j++) {
            const int tile = j / 3;
            const int s    = j - 3 * tile;
            const int e0   = (blockIdx.x + tile * 148) * 128;
            char* hb = smem + ((j & 1) ? SMEM_H1 : SMEM_H0);

            if (j >= 2) BAR_SYNC(3 + (j & 1));     // buf free?

            const float4 gv = *(const float4*)(c_W1g + s * 128 + lane * 4);
            const float4 bv = *(const float4*)(c_b1g + s * 128 + lane * 4);

            #pragma unroll 4
            for (int r = 0; r < 16; r++) {
                const int row = pw * 16 + r;
                int si, di;
                if (idx64) {
                    si = (int)((const long long*)ei)[e0 + row];
                    di = (int)((const long long*)ei)[N_EDGES + e0 + row];
                } else {
                    si = ((const int*)ei)[e0 + row];
                    di = ((const int*)ei)[N_EDGES + e0 + row];
                }
                const float gap = temporal[si] - temporal[di];
                uint2 na = *((const uint2*)(g_NAh + (size_t)si * 192 + s * 64) + lane);
                uint2 nb = *((const uint2*)(g_NBh + (size_t)di * 192 + s * 64) + lane);
                float2 a0 = h2f2(na.x), a1 = h2f2(na.y);
                float2 c0 = h2f2(nb.x), c1 = h2f2(nb.y);
                float h0 = fmaxf(a0.x + c0.x + fmaf(gap, gv.x, bv.x), 0.f);
                float h1 = fmaxf(a0.y + c0.y + fmaf(gap, gv.y, bv.y), 0.f);
                float h2 = fmaxf(a1.x + c1.x + fmaf(gap, gv.z, bv.z), 0.f);
                float h3 = fmaxf(a1.y + c1.y + fmaf(gap, gv.w, bv.w), 0.f);
                uint2 ho;
                ho.x = pack_h2(h0, h1);
                ho.y = pack_h2(h2, h3);
                *(uint2*)(hb + row * H_ROWB + lane * 8) = ho;
            }

            BAR_ARRIVE(1 + (j & 1));               // buf filled
        }
    } else {
        // =====================  CONSUMER  =====================
        const int m0   = (wid >> 1) * 32;
        const int nc0  = (wid & 1) * 64;
        const int arow = m0 + (lane & 7) + 8 * ((lane >> 3) & 1);
        const uint32_t acb = (uint32_t)(((lane >> 4) & 1) * 16);
        const int g2 = lane >> 3, rr = lane & 7;
        const uint32_t b_lane = smem_u + SMEM_W2
            + (uint32_t)(((g2 & 1) * 8 + rr) * W2_ROWB + (nc0 + (g2 >> 1) * 8) * 2);

        float acc[2][8][4];
        #pragma unroll
        for (int mi = 0; mi < 2; mi++)
            #pragma unroll
            for (int g = 0; g < 8; g++)
                #pragma unroll
                for (int q = 0; q < 4; q++) acc[mi][g][q] = 0.f;

        for (int jj = 0; jj < NP; jj++) {
            const int tile = jj / 3;
            const int s    = jj - 3 * tile;
            const uint32_t Hb = smem_u + ((jj & 1) ? SMEM_H1 : SMEM_H0);
            const uint32_t Bb = b_lane + (uint32_t)(s * 128 * W2_ROWB);

            BAR_SYNC(1 + (jj & 1));                // buf filled?

            #pragma unroll
            for (int ks = 0; ks < 8; ks++) {
                uint32_t a0f[4], a1f[4];
                LDSM_X4(a0f, Hb + (uint32_t)(arow * H_ROWB) + (uint32_t)(ks * 32) + acb);
                LDSM_X4(a1f, Hb + (uint32_t)((arow + 16) * H_ROWB) + (uint32_t)(ks * 32) + acb);
                const uint32_t bks = Bb + (uint32_t)(ks * 16 * W2_ROWB);
                #pragma unroll
                for (int np = 0; np < 4; np++) {
                    uint32_t b[4];
                    LDSM_X4T(b, bks + (uint32_t)(np * 32));
                    mma_f16(acc[0][np * 2],     a0f, b[0], b[1]);
                    mma_f16(acc[0][np * 2 + 1], a0f, b[2], b[3]);
                    mma_f16(acc[1][np * 2],     a1f, b[0], b[1]);
                    mma_f16(acc[1][np * 2 + 1], a1f, b[2], b[3]);
                }
            }

            BAR_ARRIVE(3 + (jj & 1));              // buf consumed (before epilogue)

            if (s == 2) {
                const size_t e0o = (size_t)(blockIdx.x + tile * 148) * 128;
                #pragma unroll
                for (int mi = 0; mi < 2; mi++) {
                    const size_t r0 = e0o + m0 + mi * 16 + gid;
                    #pragma unroll
                    for (int g = 0; g < 8; g++) {
                        int col = nc0 + g * 8 + qid * 2;
                        float2 bm = *(const float2*)(g_b2m + col);
                        *(float2*)(out + r0 * 128 + col) =
                            make_float2(acc[mi][g][0] * inv3 + bm.x,
                                        acc[mi][g][1] * inv3 + bm.y);
                        *(float2*)(out + (r0 + 8) * 128 + col) =
                            make_float2(acc[mi][g][2] * inv3 + bm.x,
                                        acc[mi][g][3] * inv3 + bm.y);
                        #pragma unroll
                        for (int q = 0; q < 4; q++) acc[mi][g][q] = 0.f;
                    }
                }
            }
        }
    }
}

// ---------------------------------------------------------------------------
// Launch
// ---------------------------------------------------------------------------
extern "C" void kernel_launch(void* const* d_in, const int* in_sizes, int n_in,
                              void* d_out, int out_size) {
    const float* nf = 0;
    const float* temporal = 0;
    const float* W1 = 0;
    const float* b1 = 0;
    const float* W2 = 0;
    const float* b2 = 0;
    const void*  ei = 0;

    for (int i = 0; i < n_in; i++) {
        switch (in_sizes[i]) {
            case N_NODES * D_FEAT:   nf = (const float*)d_in[i]; break;
            case N_NODES:            temporal = (const float*)d_in[i]; break;
            case SCALES * 257 * 128: W1 = (const float*)d_in[i]; break;
            case SCALES * 128 * 128: W2 = (const float*)d_in[i]; break;
            case 2 * N_EDGES:        ei = d_in[i]; break;
            case SCALES * 128:
                if (!b1) b1 = (const float*)d_in[i];
                else     b2 = (const float*)d_in[i];
                break;
            default: break;
        }
    }
    float* out = (float*)d_out;

    cudaFuncSetAttribute(node_pre_kernel, cudaFuncAttributeMaxDynamicSharedMemorySize, NP_TOT);
    cudaFuncSetAttribute(edge_kernel,     cudaFuncAttributeMaxDynamicSharedMemorySize, SMEM_TOT);

    prep_all_kernel<<<PREP_BLOCKS, 256>>>(nf, W1, W2, b1, b2, (const int*)ei);

    dim3 g1(79, 6);
    node_pre_kernel<<<g1, 256, NP_TOT>>>();

    edge_kernel<<<148, 512, SMEM_TOT>>>(temporal, ei, out);
}